// round 17
// baseline (speedup 1.0000x reference)
#include <cuda_runtime.h>
#include <cuda_fp16.h>

// Problem constants
#define BATCH 2
#define DIM   192
#define PLANE (DIM*DIM)           // 36864
#define VOL   (DIM*DIM*DIM)       // 7077888
#define NVOX  (BATCH*VOL)         // 14155776
#define RW    4                   // window radius (WIN=9)
#define WIN   9
#define INV729 (1.0f/729.0f)
#define EPSV  1e-5f
#define CHUNK 48                  // y/z chunk per block (192/48 = 4 chunks)
#define NCHUNK (DIM/CHUNK)
#define TPB12 96                  // pass12: 96 threads, each owns x = 2t, 2t+1
#define TPB3  192                 // pass3: 192 threads, one x each
#define NBLK  (BATCH*DIM*NCHUNK)  // 1536 pass3 blocks
#define PF    6                   // pass3 circular prefetch depth (MLP=6)

// Intermediates (after fused x+y pass), interleaved per voxel:
//   gBab[v] = { half2(SumI,SumJ), half2(SumI2,SumJ2) }   (one LDG.64 in pass3)
//   gB4[v]  = half(SumIJ)
__device__ uint2  gBab[NVOX];
__device__ __half gB4 [NVOX];
__device__ float    g_part[NBLK]; // per-block partial ncc sums
__device__ unsigned g_done = 0;   // last-block counter (self-resetting)

__device__ __forceinline__ unsigned h2u(__half2 h) {
    return *reinterpret_cast<unsigned*>(&h);
}
__device__ __forceinline__ __half2 u2h(unsigned u) {
    return *reinterpret_cast<__half2*>(&u);
}

// ---------------------------------------------------------------------------
// Fused pass 1+2, x-coarsened x2, BARRIER-FREE. The x-box window (+-4) is
// intra-warp data (a warp owns 64 consecutive x) except an 8-float halo at
// warp seams, which edge lanes load directly from global (L1-hit; values are
// bit-identical to what the shared row previously held). Row exchange uses
// per-warp padded buffers + __syncwarp only -> warps slide independently, so
// residency hides latency (no per-row block barrier). One-row register
// prefetch covers the LDG latency. Tap math / ring / rolling sums unchanged.
// ---------------------------------------------------------------------------
__global__ __launch_bounds__(TPB12, 10) void k_pass12(
    const float* __restrict__ I, const float* __restrict__ J)
{
    __shared__ __align__(16) uint2  rab[WIN][DIM];  // 13.8 KB {E/O voxel pairs}
    __shared__ __half r4[WIN][DIM];                 // 3.5 KB (half2 at even x)
    // per-warp padded row buffers: 36 float2 = 64 own + 4+4 halo floats
    __shared__ float2 wbI[2][3][36];                // 1.7 KB
    __shared__ float2 wbJ[2][3][36];                // 1.7 KB

    const int bz = blockIdx.x;                    // b*DIM + z
    const int y0 = blockIdx.y * CHUNK;
    const int t  = threadIdx.x;
    const int x0 = 2 * t;
    const int pb = bz * PLANE;
    const int w  = t >> 5;                        // warp id (0..2)
    const int ln = t & 31;                        // lane
    const int wb = w * 64;                        // warp's first x

    // halo duty: lanes 0,1 load the left 2 float2s; lanes 30,31 the right 2.
    const bool edge = (ln < 2) || (ln >= 30);
    const int  hx   = (ln < 2) ? (wb - 4 + 2*ln) : (wb + 64 + 2*(ln - 30));
    const bool hval = edge && (hx >= 0) && (hx <= DIM - 2);
    const int  hp   = (ln < 2) ? ln : (34 + (ln - 30));   // float2 slot

    // rolling sums, packed: E=(x0), O=(x0+1); s4EO = (E4, O4)
    const __half2 hz = __floats2half2_rn(0.f, 0.f);
    __half2 sE01 = hz, sE23 = hz, sO01 = hz, sO23 = hz, s4EO = hz;

    const int rlo  = (y0 - RW < 0) ? 0 : (y0 - RW);
    const int rmax = (y0 + CHUNK - 1 + RW < DIM - 1) ? (y0 + CHUNK - 1 + RW)
                                                     : (DIM - 1);
    const float2 fz = make_float2(0.f, 0.f);

    // prefetched input row (registers): own pair + (edge lanes) halo pair
    float2 p_iv = *reinterpret_cast<const float2*>(&I[pb + rlo*DIM + x0]);
    float2 p_jv = *reinterpret_cast<const float2*>(&J[pb + rlo*DIM + x0]);
    float2 p_hi = hval ? *reinterpret_cast<const float2*>(&I[pb + rlo*DIM + hx]) : fz;
    float2 p_hj = hval ? *reinterpret_cast<const float2*>(&J[pb + rlo*DIM + hx]) : fz;

    auto proc = [&](int r) {
        const int par = r & 1;
        wbI[par][w][2 + ln] = p_iv;               // own pair at slot 2+ln
        wbJ[par][w][2 + ln] = p_jv;
        if (edge) { wbI[par][w][hp] = p_hi; wbJ[par][w][hp] = p_hj; }
        if (r < rmax) {                           // prefetch next row
            const int nb = pb + (r + 1) * DIM;
            p_iv = *reinterpret_cast<const float2*>(&I[nb + x0]);
            p_jv = *reinterpret_cast<const float2*>(&J[nb + x0]);
            p_hi = hval ? *reinterpret_cast<const float2*>(&I[nb + hx]) : fz;
            p_hj = hval ? *reinterpret_cast<const float2*>(&J[nb + hx]) : fz;
        }
        __syncwarp();

        // 10 taps w[0..9] = x0-4 .. x0+5 : 5 consecutive float2 slots ln+m
        float S0=0.f,S1=0.f,S2=0.f,S3=0.f,S4=0.f;
        float u0=0.f,v0=0.f,u9=0.f,v9=0.f;
#pragma unroll
        for (int m = 0; m < 5; m++) {
            const float2 uu = wbI[par][w][ln + m];
            const float2 vv = wbJ[par][w][ln + m];
            if (m == 0) { u0 = uu.x; v0 = vv.x; }
            if (m == 4) { u9 = uu.y; v9 = vv.y; }
            S0 += uu.x; S1 += vv.x; S2 += uu.x*uu.x; S3 += vv.x*vv.x; S4 += uu.x*vv.x;
            S0 += uu.y; S1 += vv.y; S2 += uu.y*uu.y; S3 += vv.y*vv.y; S4 += uu.y*vv.y;
        }
        // even = 10-tap sum minus tap9; odd = minus tap0. Pack once.
        const __half2 e01 = __floats2half2_rn(S0 - u9,    S1 - v9);
        const __half2 e23 = __floats2half2_rn(S2 - u9*u9, S3 - v9*v9);
        const __half2 o01 = __floats2half2_rn(S0 - u0,    S1 - v0);
        const __half2 o23 = __floats2half2_rn(S2 - u0*u0, S3 - v0*v0);
        const __half2 eo4 = __floats2half2_rn(S4 - u9*v9, S4 - u0*v0);

        const int sl = r % WIN;
        *reinterpret_cast<uint4*>(&rab[sl][x0]) =
            make_uint4(h2u(e01), h2u(e23), h2u(o01), h2u(o23));
        *reinterpret_cast<__half2*>(&r4[sl][x0]) = eo4;

        sE01 = __hadd2(sE01, e01); sE23 = __hadd2(sE23, e23);
        sO01 = __hadd2(sO01, o01); sO23 = __hadd2(sO23, o23);
        s4EO = __hadd2(s4EO, eo4);
    };

    for (int r = rlo; r <= y0 + RW; r++) proc(r);

    for (int y = y0; ; y++) {
        const int id = pb + y * DIM + x0;
        *reinterpret_cast<uint4*>(&gBab[id]) =
            make_uint4(h2u(sE01), h2u(sE23), h2u(sO01), h2u(sO23));
        *reinterpret_cast<__half2*>(&gB4[id]) = s4EO;
        if (y == y0 + CHUNK - 1) break;

        const int rs = y - RW;                    // leaving row
        if (rs >= 0) {
            const int sl = rs % WIN;
            const uint4 q = *reinterpret_cast<const uint4*>(&rab[sl][x0]);
            const __half2 q4 = *reinterpret_cast<const __half2*>(&r4[sl][x0]);
            sE01 = __hsub2(sE01, u2h(q.x)); sE23 = __hsub2(sE23, u2h(q.y));
            sO01 = __hsub2(sO01, u2h(q.z)); sO23 = __hsub2(sO23, u2h(q.w));
            s4EO = __hsub2(s4EO, q4);
        }
        const int ra = y + RW + 1;                // entering row
        if (ra < DIM) proc(ra);
    }
}

// ---------------------------------------------------------------------------
// Pass 3: z-rolling sums, register ring (fully unrolled, slot = i%9 static),
// CIRCULAR prefetch buffer of depth PF=6: at iteration i, consume pf[i%PF]
// then immediately refill that slot with the load for iteration i+PF. Six
// loads in flight per thread at the same register budget as the old 2x4
// double buffer. Arithmetic order identical. Grid-wide final reduction
// folded in (fence + atomic counter, deterministic, self-resetting).
// ---------------------------------------------------------------------------
__global__ __launch_bounds__(TPB3, 4) void k_pass3(float* __restrict__ out) {
    __shared__ float red[TPB3];
    __shared__ int   s_last;

    const int by = blockIdx.x;                    // b*DIM + y
    const int b  = by / DIM;
    const int y  = by % DIM;
    const int z0 = blockIdx.y * CHUNK;
    const int x  = threadIdx.x;
    const int base = b * VOL + y * DIM + x;

    const __half2 hz = __floats2half2_rn(0.f, 0.f);
    const __half  h0 = __float2half_rn(0.f);

    uint2  qab[WIN];                              // register ring
    __half q4 [WIN];
    __half2 s01 = hz, s23 = hz;
    __half  s4  = h0;

    // Prologue: 9 slots, rows z0-4 .. z0+4 (rows < 0 are virtual zeros).
#pragma unroll
    for (int l = 0; l < WIN; l++) {
        const int r = z0 - RW + l;                // always < DIM
        uint2 uab = make_uint2(0u, 0u);
        __half h4 = h0;
        if (r >= 0) {
            const int id = base + r * PLANE;
            uab = gBab[id];
            h4  = gB4[id];
        }
        qab[l] = uab; q4[l] = h4;
        s01 = __hadd2(s01, u2h(uab.x));
        s23 = __hadd2(s23, u2h(uab.y));
        s4  = __hadd(s4, h4);
    }

    // Circular prefetch buffer: pf[i%PF] holds the entering row for iter i.
    uint2  pf_ab[PF];
    __half pf_4 [PF];

    auto pload = [&](int k, uint2& uab, __half& h4) {
        uab = make_uint2(0u, 0u);
        h4  = h0;
        if (k < CHUNK - 1) {
            const int ra = z0 + RW + 1 + k;
            if (ra < DIM) {
                const int id = base + ra * PLANE;
                uab = gBab[id];
                h4  = gB4[id];
            }
        }
    };

#pragma unroll
    for (int j = 0; j < PF; j++) pload(j, pf_ab[j], pf_4[j]);

    float acc = 0.f;
#pragma unroll
    for (int i = 0; i < CHUNK; i++) {
        const int ps = i % PF;                    // static after unroll
        const uint2  e_ab = pf_ab[ps];            // consume slot...
        const __half e_4  = pf_4 [ps];
        pload(i + PF, pf_ab[ps], pf_4[ps]);       // ...then refill (iter i+PF)

        const float2 f01 = __half22float2(s01);
        const float2 f23 = __half22float2(s23);
        const float  f4  = __half2float(s4);
        const float uI = f01.x * INV729, uJ = f01.y * INV729;
        const float I2 = f23.x * INV729 - uI * uI;
        const float J2 = f23.y * INV729 - uJ * uJ;
        const float IJ = f4   * INV729 - uI * uJ;
        acc += (IJ * IJ) / (I2 * J2 + EPSV);

        if (i < CHUNK - 1) {
            const int sl = i % WIN;               // static after unroll
            s01 = __hsub2(s01, u2h(qab[sl].x));   // leaving row (exact)
            s23 = __hsub2(s23, u2h(qab[sl].y));
            s4  = __hsub(s4, q4[sl]);
            qab[sl] = e_ab; q4[sl] = e_4;         // entering row -> same slot
            s01 = __hadd2(s01, u2h(e_ab.x));
            s23 = __hadd2(s23, u2h(e_ab.y));
            s4  = __hadd(s4, e_4);
        }
    }

    // Block tree-reduce 192 partials (192 = 3 * 2^6), deterministic order.
    red[x] = acc;
    __syncthreads();
#pragma unroll
    for (int s = 96; s >= 3; s >>= 1) {
        if (x < s) red[x] += red[x + s];
        __syncthreads();
    }
    if (x == 0) {
        g_part[blockIdx.y * (BATCH * DIM) + blockIdx.x] = red[0] + red[1] + red[2];
        __threadfence();
        const unsigned v = atomicAdd(&g_done, 1u);
        s_last = (v == NBLK - 1);
    }
    __syncthreads();

    if (s_last) {                                 // exactly one block runs this
        float a = 0.f;
        for (int i = x; i < NBLK; i += TPB3) a += g_part[i];
        red[x] = a;
        __syncthreads();
#pragma unroll
        for (int s = 96; s >= 3; s >>= 1) {
            if (x < s) red[x] += red[x + s];
            __syncthreads();
        }
        if (x == 0) {
            out[0] = -(red[0] + red[1] + red[2]) * (1.0f / (float)NVOX);
            g_done = 0;                           // reset for next graph replay
        }
    }
}

extern "C" void kernel_launch(void* const* d_in, const int* in_sizes, int n_in,
                              void* d_out, int out_size) {
    const float* y_pred = (const float*)d_in[0];
    const float* y_true = (const float*)d_in[1];
    float* out = (float*)d_out;

    k_pass12<<<dim3(BATCH * DIM, NCHUNK), TPB12>>>(y_pred, y_true);
    k_pass3 <<<dim3(BATCH * DIM, NCHUNK), TPB3>>>(out);
}